// round 5
// baseline (speedup 1.0000x reference)
#include <cuda_runtime.h>
#include <math.h>

#define NN 50000
#define NE 800000

// ---------------- device scratch (allocation-free) ----------------
__device__ float g_buf1[NN * 512];
__device__ float g_buf2[NN * 512];
__device__ float g_dis[NN];
__device__ int   g_indeg[NN];
__device__ int   g_rowptr[NN + 1];
__device__ int   g_cursor[NN];
__device__ int   g_col[NE];
__device__ float g_val[NE];
__device__ float g_Wall[256 * 72];
__device__ float g_ball[72];

// ---------------- packed f32x2 helpers ----------------
__device__ __forceinline__ unsigned long long pack2f(float x) {
    unsigned long long r;
    asm("mov.b64 %0, {%1, %1};" : "=l"(r) : "f"(x));
    return r;
}
__device__ __forceinline__ void fma2(unsigned long long& acc,
                                     unsigned long long a,
                                     unsigned long long b) {
    asm("fma.rn.f32x2 %0, %1, %2, %0;" : "+l"(acc) : "l"(a), "l"(b));
}
__device__ __forceinline__ float2 unpack2(unsigned long long v) {
    float2 r;
    r.x = __uint_as_float((unsigned int)(v & 0xffffffffull));
    r.y = __uint_as_float((unsigned int)(v >> 32));
    return r;
}

// ---------------- CSR build kernels ----------------
__global__ void zero_indeg_kernel() {
    int i = blockIdx.x * blockDim.x + threadIdx.x;
    if (i < NN) g_indeg[i] = 0;
}
__global__ void count_kernel(const int* __restrict__ dst) {
    int e = blockIdx.x * blockDim.x + threadIdx.x;
    if (e < NE) atomicAdd(&g_indeg[dst[e]], 1);
}
__global__ void dis_kernel() {
    int i = blockIdx.x * blockDim.x + threadIdx.x;
    if (i < NN) g_dis[i] = rsqrtf((float)(g_indeg[i] + 1));
}
// Single-block exclusive scan of g_indeg -> g_rowptr, g_cursor
__global__ void scan_kernel() {
    __shared__ int warpsums[32];
    __shared__ int s_carry;
    const int tid = threadIdx.x;  // 1024 threads
    if (tid == 0) s_carry = 0;
    __syncthreads();
    for (int base = 0; base < NN; base += 1024) {
        int i = base + tid;
        int v = (i < NN) ? g_indeg[i] : 0;
        int x = v;
        #pragma unroll
        for (int o = 1; o < 32; o <<= 1) {
            int t = __shfl_up_sync(0xffffffffu, x, o);
            if ((tid & 31) >= o) x += t;
        }
        if ((tid & 31) == 31) warpsums[tid >> 5] = x;
        __syncthreads();
        if (tid < 32) {
            int s = warpsums[tid];
            #pragma unroll
            for (int o = 1; o < 32; o <<= 1) {
                int t = __shfl_up_sync(0xffffffffu, s, o);
                if (tid >= o) s += t;
            }
            warpsums[tid] = s;
        }
        __syncthreads();
        int wofs = (tid >= 32) ? warpsums[(tid >> 5) - 1] : 0;
        int incl = x + wofs;
        int excl = incl - v + s_carry;
        if (i < NN) {
            g_rowptr[i] = excl;
            g_cursor[i] = excl;
        }
        __syncthreads();
        if (tid == 1023) s_carry += incl;  // chunk total
        __syncthreads();
    }
    if (tid == 0) g_rowptr[NN] = s_carry;
}
__global__ void scatter_kernel(const int* __restrict__ src, const int* __restrict__ dst) {
    int e = blockIdx.x * blockDim.x + threadIdx.x;
    if (e < NE) {
        int s = src[e], d = dst[e];
        int p = atomicAdd(&g_cursor[d], 1);
        g_col[p] = s;
        g_val[p] = g_dis[s] * g_dis[d];
    }
}

// ---------------- GEMM: C[M,N] = A[M,K] @ B[K,N] (+ optional bias) ----------------
// 128x128x16 tile, 256 threads, 8x8 micro-tile via packed f32x2 FMA.
__global__ __launch_bounds__(256) void gemm_kernel(
    const float* __restrict__ A, const float* __restrict__ B,
    float* __restrict__ C, const float* __restrict__ bias,
    int M, int N, int K)
{
    __shared__ __align__(16) float As[2][16][132];
    __shared__ __align__(16) float Bs[2][16][128];

    const int tid = threadIdx.x;
    const int tx = tid & 15;       // N direction (16)
    const int ty = tid >> 4;       // M direction (16)
    const int bm = blockIdx.y * 128;
    const int bn = blockIdx.x * 128;

    const int arow = tid >> 2;         // 0..63
    const int ak   = (tid & 3) << 2;   // 0,4,8,12
    const int brow = tid >> 5;         // 0..7
    const int bcol = (tid & 31) << 2;  // 0..124

    const bool fullN = (bn + 128 <= N);

    float4 a0, a1, b0, b1;

    auto gload = [&](int kt) {
        int r0 = bm + arow, r1 = r0 + 64;
        a0 = (r0 < M) ? *(const float4*)(A + r0 * K + kt + ak) : make_float4(0.f, 0.f, 0.f, 0.f);
        a1 = (r1 < M) ? *(const float4*)(A + r1 * K + kt + ak) : make_float4(0.f, 0.f, 0.f, 0.f);
        int c = bn + bcol;
        const float* Bp0 = B + (kt + brow) * N;
        const float* Bp1 = B + (kt + brow + 8) * N;
        if (fullN) {
            b0 = *(const float4*)(Bp0 + c);
            b1 = *(const float4*)(Bp1 + c);
        } else {
            b0.x = (c + 0 < N) ? Bp0[c + 0] : 0.f;
            b0.y = (c + 1 < N) ? Bp0[c + 1] : 0.f;
            b0.z = (c + 2 < N) ? Bp0[c + 2] : 0.f;
            b0.w = (c + 3 < N) ? Bp0[c + 3] : 0.f;
            b1.x = (c + 0 < N) ? Bp1[c + 0] : 0.f;
            b1.y = (c + 1 < N) ? Bp1[c + 1] : 0.f;
            b1.z = (c + 2 < N) ? Bp1[c + 2] : 0.f;
            b1.w = (c + 3 < N) ? Bp1[c + 3] : 0.f;
        }
    };
    auto sstore = [&](int bi) {
        As[bi][ak + 0][arow] = a0.x;  As[bi][ak + 1][arow] = a0.y;
        As[bi][ak + 2][arow] = a0.z;  As[bi][ak + 3][arow] = a0.w;
        As[bi][ak + 0][arow + 64] = a1.x;  As[bi][ak + 1][arow + 64] = a1.y;
        As[bi][ak + 2][arow + 64] = a1.z;  As[bi][ak + 3][arow + 64] = a1.w;
        *(float4*)&Bs[bi][brow][bcol]     = b0;
        *(float4*)&Bs[bi][brow + 8][bcol] = b1;
    };

    unsigned long long acc[8][4];
    #pragma unroll
    for (int i = 0; i < 8; i++)
        #pragma unroll
        for (int j = 0; j < 4; j++) acc[i][j] = 0ull;

    auto compute = [&](int bi) {
        #pragma unroll
        for (int k = 0; k < 16; k++) {
            float4 av0 = *(const float4*)&As[bi][k][ty << 2];
            float4 av1 = *(const float4*)&As[bi][k][(ty << 2) + 64];
            ulonglong2 bv0 = *(const ulonglong2*)&Bs[bi][k][tx << 2];
            ulonglong2 bv1 = *(const ulonglong2*)&Bs[bi][k][(tx << 2) + 64];
            unsigned long long ap[8];
            ap[0] = pack2f(av0.x); ap[1] = pack2f(av0.y);
            ap[2] = pack2f(av0.z); ap[3] = pack2f(av0.w);
            ap[4] = pack2f(av1.x); ap[5] = pack2f(av1.y);
            ap[6] = pack2f(av1.z); ap[7] = pack2f(av1.w);
            #pragma unroll
            for (int m = 0; m < 8; m++) {
                fma2(acc[m][0], ap[m], bv0.x);
                fma2(acc[m][1], ap[m], bv0.y);
                fma2(acc[m][2], ap[m], bv1.x);
                fma2(acc[m][3], ap[m], bv1.y);
            }
        }
    };

    gload(0);
    sstore(0);
    __syncthreads();

    const int nT = K >> 4;
    int buf = 0;
    for (int t = 1; t < nT; ++t) {
        gload(t << 4);
        compute(buf);
        buf ^= 1;
        sstore(buf);
        __syncthreads();
    }
    compute(buf);

    // epilogue
    #pragma unroll
    for (int mi = 0; mi < 8; mi++) {
        int r = bm + (ty << 2) + ((mi < 4) ? mi : (mi - 4 + 64));
        if (r >= M) continue;
        float* Crow = C + r * N;
        #pragma unroll
        for (int p = 0; p < 4; p++) {
            int c = bn + (tx << 2) + ((p & 1) << 1) + ((p >> 1) << 6);
            float2 v = unpack2(acc[mi][p]);
            if (c < N) {
                float add = bias ? bias[c] : 0.f;
                Crow[c] = v.x + add;
            }
            if (c + 1 < N) {
                float add = bias ? bias[c + 1] : 0.f;
                Crow[c + 1] = v.y + add;
            }
        }
    }
}

// ---------------- aggregation: out[i] = bias + dis[i]^2*Y[i] + sum_e val*Y[col] ----------------
template <int D, int RELU>
__global__ __launch_bounds__(128) void aggregate_kernel(
    const float* __restrict__ Y, float* __restrict__ out, const float* __restrict__ bias)
{
    constexpr int TPN = D / 4;  // threads per node
    int gt = blockIdx.x * 128 + threadIdx.x;
    int node = gt / TPN;
    int lane = gt % TPN;
    if (node >= NN) return;
    int c = lane << 2;

    float dv = g_dis[node];
    float w = dv * dv;
    float4 acc = *(const float4*)(bias + c);
    float4 y = *(const float4*)(Y + node * D + c);
    acc.x = fmaf(w, y.x, acc.x);
    acc.y = fmaf(w, y.y, acc.y);
    acc.z = fmaf(w, y.z, acc.z);
    acc.w = fmaf(w, y.w, acc.w);

    int e0 = g_rowptr[node], e1 = g_rowptr[node + 1];
    for (int p = e0; p < e1; ++p) {
        int j = __ldg(&g_col[p]);
        float v = __ldg(&g_val[p]);
        float4 yj = *(const float4*)(Y + j * D + c);
        acc.x = fmaf(v, yj.x, acc.x);
        acc.y = fmaf(v, yj.y, acc.y);
        acc.z = fmaf(v, yj.z, acc.z);
        acc.w = fmaf(v, yj.w, acc.w);
    }
    if (RELU) {
        acc.x = fmaxf(acc.x, 0.f);
        acc.y = fmaxf(acc.y, 0.f);
        acc.z = fmaxf(acc.z, 0.f);
        acc.w = fmaxf(acc.w, 0.f);
    }
    *(float4*)(out + node * D + c) = acc;
}

// ---------------- head weight packing / output split ----------------
__global__ void pack_heads_kernel(
    const float* __restrict__ We, const float* __restrict__ be,
    const float* __restrict__ Wh, const float* __restrict__ bh,
    const float* __restrict__ Wg, const float* __restrict__ bg)
{
    int idx = blockIdx.x * blockDim.x + threadIdx.x;
    if (idx < 256 * 72) {
        int k = idx / 72, j = idx % 72;
        float v;
        if (j < 7)       v = We[k * 7 + j];
        else if (j < 15) v = Wh[k * 8 + (j - 7)];
        else             v = Wg[k * 57 + (j - 15)];
        g_Wall[idx] = v;
    }
    if (idx < 72) {
        float v;
        if (idx < 7)       v = be[idx];
        else if (idx < 15) v = bh[idx - 7];
        else               v = bg[idx - 15];
        g_ball[idx] = v;
    }
}

__global__ void split_heads_kernel(const float* __restrict__ T,
                                   float* __restrict__ outE,
                                   float* __restrict__ outH,
                                   float* __restrict__ outG)
{
    int idx = blockIdx.x * blockDim.x + threadIdx.x;
    if (idx >= NN * 72) return;
    int i = idx / 72, j = idx % 72;
    float v = T[idx];
    if (j < 7)       outE[i * 7 + j] = v;
    else if (j < 15) outH[i * 8 + (j - 7)] = v;
    else             outG[i * 57 + (j - 15)] = v;
}

// ---------------- launch ----------------
extern "C" void kernel_launch(void* const* d_in, const int* in_sizes, int n_in,
                              void* d_out, int out_size)
{
    const float* x  = (const float*)d_in[0];
    const int*   ei = (const int*)d_in[1];
    const float* W1 = (const float*)d_in[2];
    const float* b1 = (const float*)d_in[3];
    const float* W2 = (const float*)d_in[4];
    const float* b2 = (const float*)d_in[5];
    const float* W3 = (const float*)d_in[6];
    const float* b3 = (const float*)d_in[7];
    const float* We = (const float*)d_in[8];
    const float* be = (const float*)d_in[9];
    const float* Wh = (const float*)d_in[10];
    const float* bh = (const float*)d_in[11];
    const float* Wg = (const float*)d_in[12];
    const float* bg = (const float*)d_in[13];

    const int* srcArr = ei;        // edge_index[0]
    const int* dstArr = ei + NE;   // edge_index[1]

    float* out  = (float*)d_out;
    float* emb  = out;                            // [NN, 256]
    float* outE = out + (size_t)NN * 256;         // [NN, 7]
    float* outH = outE + (size_t)NN * 7;          // [NN, 8]
    float* outG = outH + (size_t)NN * 8;          // [NN, 57]

    float *buf1, *buf2, *Wall, *ball;
    cudaGetSymbolAddress((void**)&buf1, g_buf1);
    cudaGetSymbolAddress((void**)&buf2, g_buf2);
    cudaGetSymbolAddress((void**)&Wall, g_Wall);
    cudaGetSymbolAddress((void**)&ball, g_ball);

    // ---- CSR build (recomputed each call; deterministic integer work) ----
    zero_indeg_kernel<<<(NN + 255) / 256, 256>>>();
    count_kernel<<<(NE + 255) / 256, 256>>>(dstArr);
    dis_kernel<<<(NN + 255) / 256, 256>>>();
    scan_kernel<<<1, 1024>>>();
    scatter_kernel<<<(NE + 255) / 256, 256>>>(srcArr, dstArr);

    const int mblocks = (NN + 127) / 128;

    // layer 1: h1 = relu(Agg(x @ W1) + b1)
    gemm_kernel<<<dim3(4, mblocks), 256>>>(x, W1, buf1, nullptr, NN, 512, 512);
    aggregate_kernel<512, 1><<<NN, 128>>>(buf1, buf2, b1);
    // layer 2
    gemm_kernel<<<dim3(4, mblocks), 256>>>(buf2, W2, buf1, nullptr, NN, 512, 512);
    aggregate_kernel<512, 1><<<NN, 128>>>(buf1, buf2, b2);
    // layer 3: emb (no relu) -> directly into output
    gemm_kernel<<<dim3(2, mblocks), 256>>>(buf2, W3, buf1, nullptr, NN, 256, 512);
    aggregate_kernel<256, 0><<<NN / 2, 128>>>(buf1, emb, b3);
    // heads: one packed GEMM [NN,256]@[256,72]+b, then split into 3 regions
    pack_heads_kernel<<<(256 * 72 + 255) / 256, 256>>>(We, be, Wh, bh, Wg, bg);
    gemm_kernel<<<dim3(1, mblocks), 256>>>(emb, Wall, buf2, ball, NN, 72, 256);
    split_heads_kernel<<<(NN * 72 + 255) / 256, 256>>>(buf2, outE, outH, outG);
}

// round 7
// speedup vs baseline: 1.3708x; 1.3708x over previous
#include <cuda_runtime.h>
#include <cuda_bf16.h>
#include <math.h>
#include <stdint.h>

#define NN 50000
#define NE 800000
#define MPAD 50048   // 391 * 128

// ---------------- device scratch (allocation-free) ----------------
__device__ float g_buf1[NN * 512];          // GEMM f32 output
__device__ float g_buf2[NN * 512];          // heads temp
__device__ __nv_bfloat16 g_A2[(size_t)MPAD * 1024];   // [Ah | Al] bf16, K-contig rows
__device__ __nv_bfloat16 g_Bt1[512 * 1024];           // [Bh | Bl], N-major rows, K-contig
__device__ __nv_bfloat16 g_Bt2[512 * 1024];
__device__ __nv_bfloat16 g_Bt3[256 * 1024];
__device__ float g_dis[NN];
__device__ int   g_indeg[NN];
__device__ int   g_rowptr[NN + 1];
__device__ int   g_cursor[NN];
__device__ int   g_col[NE];
__device__ float g_val[NE];
__device__ float g_Wall[256 * 72];
__device__ float g_ball[72];
__device__ int   g_blocksum[64];

// ---------------- helpers ----------------
__device__ __forceinline__ uint32_t smem_u32(const void* p) {
    uint32_t a;
    asm("{ .reg .u64 t; cvta.to.shared.u64 t, %1; cvt.u32.u64 %0, t; }" : "=r"(a) : "l"(p));
    return a;
}
__device__ __forceinline__ void ldsm4(uint32_t* r, uint32_t addr) {
    asm volatile("ldmatrix.sync.aligned.m8n8.x4.shared.b16 {%0,%1,%2,%3}, [%4];"
                 : "=r"(r[0]), "=r"(r[1]), "=r"(r[2]), "=r"(r[3]) : "r"(addr));
}
__device__ __forceinline__ void mma16816(float* c, const uint32_t* a, const uint32_t* b) {
    asm volatile("mma.sync.aligned.m16n8k16.row.col.f32.bf16.bf16.f32 "
                 "{%0,%1,%2,%3}, {%4,%5,%6,%7}, {%8,%9}, {%0,%1,%2,%3};"
                 : "+f"(c[0]), "+f"(c[1]), "+f"(c[2]), "+f"(c[3])
                 : "r"(a[0]), "r"(a[1]), "r"(a[2]), "r"(a[3]), "r"(b[0]), "r"(b[1]));
}

// ---------------- CSR build ----------------
__global__ void zero_indeg_kernel() {
    int i = blockIdx.x * blockDim.x + threadIdx.x;
    if (i < NN) g_indeg[i] = 0;
}
__global__ void count_kernel(const int* __restrict__ dst) {
    int e = blockIdx.x * blockDim.x + threadIdx.x;
    if (e < NE) atomicAdd(&g_indeg[dst[e]], 1);
}
__global__ void dis_kernel() {
    int i = blockIdx.x * blockDim.x + threadIdx.x;
    if (i < NN) g_dis[i] = rsqrtf((float)(g_indeg[i] + 1));
}
__global__ void scan_part1() {   // grid 49, block 1024: block sums
    __shared__ int ws[32];
    int i = blockIdx.x * 1024 + threadIdx.x;
    int v = (i < NN) ? g_indeg[i] : 0;
    #pragma unroll
    for (int o = 16; o > 0; o >>= 1) v += __shfl_down_sync(0xffffffffu, v, o);
    if ((threadIdx.x & 31) == 0) ws[threadIdx.x >> 5] = v;
    __syncthreads();
    if (threadIdx.x < 32) {
        int s = ws[threadIdx.x];
        #pragma unroll
        for (int o = 16; o > 0; o >>= 1) s += __shfl_down_sync(0xffffffffu, s, o);
        if (threadIdx.x == 0) g_blocksum[blockIdx.x] = s;
    }
}
__global__ void scan_part2() {   // 1 thread
    int acc = 0;
    for (int b = 0; b < 49; ++b) { int t = g_blocksum[b]; g_blocksum[b] = acc; acc += t; }
    g_rowptr[NN] = acc;
}
__global__ void scan_part3() {   // grid 49, block 1024: local scan + offset
    __shared__ int ws[32];
    int tid = threadIdx.x;
    int i = blockIdx.x * 1024 + tid;
    int v = (i < NN) ? g_indeg[i] : 0;
    int x = v;
    #pragma unroll
    for (int o = 1; o < 32; o <<= 1) {
        int t = __shfl_up_sync(0xffffffffu, x, o);
        if ((tid & 31) >= o) x += t;
    }
    if ((tid & 31) == 31) ws[tid >> 5] = x;
    __syncthreads();
    if (tid < 32) {
        int s = ws[tid];
        #pragma unroll
        for (int o = 1; o < 32; o <<= 1) {
            int t = __shfl_up_sync(0xffffffffu, s, o);
            if (tid >= o) s += t;
        }
        ws[tid] = s;
    }
    __syncthreads();
    int wofs = (tid >= 32) ? ws[(tid >> 5) - 1] : 0;
    int excl = x + wofs - v + g_blocksum[blockIdx.x];
    if (i < NN) { g_rowptr[i] = excl; g_cursor[i] = excl; }
}
__global__ void scatter_kernel(const int* __restrict__ src, const int* __restrict__ dst) {
    int e = blockIdx.x * blockDim.x + threadIdx.x;
    if (e < NE) {
        int s = src[e], d = dst[e];
        int p = atomicAdd(&g_cursor[d], 1);
        g_col[p] = s;
        g_val[p] = g_dis[s] * g_dis[d];
    }
}

// ---------------- bf16 split conversions ----------------
__device__ __forceinline__ uint32_t pack_bf2(float a, float b) {
    __nv_bfloat162 h = __floats2bfloat162_rn(a, b);
    return *(uint32_t*)&h;
}
__device__ __forceinline__ void split4(const float4& v, uint2& hi, uint2& lo) {
    __nv_bfloat16 hx = __float2bfloat16_rn(v.x), hy = __float2bfloat16_rn(v.y);
    __nv_bfloat16 hz = __float2bfloat16_rn(v.z), hw = __float2bfloat16_rn(v.w);
    float lx = v.x - __bfloat162float(hx), ly = v.y - __bfloat162float(hy);
    float lz = v.z - __bfloat162float(hz), lw = v.w - __bfloat162float(hw);
    __nv_bfloat162 h01 = __floats2bfloat162_rn(__bfloat162float(hx), __bfloat162float(hy));
    __nv_bfloat162 h23 = __floats2bfloat162_rn(__bfloat162float(hz), __bfloat162float(hw));
    hi.x = *(uint32_t*)&h01; hi.y = *(uint32_t*)&h23;
    lo.x = pack_bf2(lx, ly); lo.y = pack_bf2(lz, lw);
}

__global__ void convert_x_kernel(const float* __restrict__ X) {
    int idx = blockIdx.x * 256 + threadIdx.x;
    if (idx >= MPAD * 128) return;
    int row = idx >> 7, col = (idx & 127) << 2;
    uint2 hi = make_uint2(0, 0), lo = make_uint2(0, 0);
    if (row < NN) {
        float4 v = *(const float4*)(X + (size_t)row * 512 + col);
        split4(v, hi, lo);
    }
    *(uint2*)(g_A2 + (size_t)row * 1024 + col) = hi;
    *(uint2*)(g_A2 + (size_t)row * 1024 + 512 + col) = lo;
}

// W [K=512][N] f32 -> Bt [N][1024] bf16 ([Bh|Bl]), N-major rows
__global__ void convert_B_kernel(const float* __restrict__ W, __nv_bfloat16* __restrict__ Bt, int N) {
    int idx = blockIdx.x * 256 + threadIdx.x;
    if (idx >= 512 * N) return;
    int k = idx / N, n = idx % N;
    float v = W[idx];
    __nv_bfloat16 hi = __float2bfloat16_rn(v);
    float l = v - __bfloat162float(hi);
    Bt[(size_t)n * 1024 + k] = hi;
    Bt[(size_t)n * 1024 + 512 + k] = __float2bfloat16_rn(l);
}

// ---------------- mma.sync GEMM: C[M,N] = A2 @ Bt^T (3-term bf16 split, fp32 accum) ----
// A2: [MPAD,1024] bf16 K-contig. Bt: [N,1024] bf16 K-contig. 48 K-stages of 32.
// CTA 128x128, 8 warps of 64x32. Smem rows strided 40 elems (80B) => conflict-free ldmatrix.
#define SROW 40
#define SSTAGE (128 * SROW)
__global__ __launch_bounds__(256) void gemm_mma_kernel(
    const __nv_bfloat16* __restrict__ A2, const __nv_bfloat16* __restrict__ Bt,
    float* __restrict__ C, int M, int N)
{
    __shared__ __align__(16) __nv_bfloat16 As[2][128][SROW];
    __shared__ __align__(16) __nv_bfloat16 Bs[2][128][SROW];

    const int tid = threadIdx.x;
    const int wid = tid >> 5, lane = tid & 31;
    const int bm = blockIdx.y * 128;
    const int bn = blockIdx.x * 128;
    const int warp_m = (wid >> 2) * 64;   // 0 or 64
    const int warp_n = (wid & 3) * 32;    // 0..96

    const uint32_t as_u32 = smem_u32(As);
    const uint32_t bs_u32 = smem_u32(Bs);

    const int lrow = tid >> 2;        // 0..63 (x2 via i loop)
    const int lseg = (tid & 3) << 3;  // element offset 0,8,16,24

    uint4 ra[2], rb[2];
    auto gload = [&](int s) {
        int term = s >> 4, kk = (s & 15) << 5;
        int ac = ((term == 1) ? 512 : 0) + kk;   // A: Ah, Al, Ah
        int bc = ((term == 2) ? 512 : 0) + kk;   // B: Bh, Bh, Bl
        #pragma unroll
        for (int i = 0; i < 2; ++i) {
            int row = lrow + i * 64;
            ra[i] = *(const uint4*)(A2 + (size_t)(bm + row) * 1024 + ac + lseg);
            rb[i] = *(const uint4*)(Bt + (size_t)(bn + row) * 1024 + bc + lseg);
        }
    };
    auto sstore = [&](int bi) {
        #pragma unroll
        for (int i = 0; i < 2; ++i) {
            int row = lrow + i * 64;
            *(uint4*)&As[bi][row][lseg] = ra[i];
            *(uint4*)&Bs[bi][row][lseg] = rb[i];
        }
    };

    float acc[4][4][4];
    #pragma unroll
    for (int mi = 0; mi < 4; mi++)
        #pragma unroll
        for (int ni = 0; ni < 4; ni++)
            #pragma unroll
            for (int j = 0; j < 4; j++) acc[mi][ni][j] = 0.f;

    // ldmatrix source addresses (constant per thread, plus stage/k offsets)
    const uint32_t a_lm = as_u32 + (uint32_t)(warp_m + (lane & 15)) * (SROW * 2) + ((lane >> 4) << 4);
    const int bq = lane >> 3;  // 0..3
    const uint32_t b_lm = bs_u32 + (uint32_t)(warp_n + ((bq >> 1) << 3) + (lane & 7)) * (SROW * 2)
                          + ((bq & 1) << 4);

    auto compute = [&](int bi) {
        uint32_t aoffb = (uint32_t)bi * (SSTAGE * 2);
        #pragma unroll
        for (int ks = 0; ks < 2; ++ks) {        // two k16 steps (bytes: ks*32)
            uint32_t a[4][4], b[4][2];
            #pragma unroll
            for (int mi = 0; mi < 4; mi++)
                ldsm4(a[mi], a_lm + aoffb + (uint32_t)mi * 16 * (SROW * 2) + ks * 32);
            #pragma unroll
            for (int nb = 0; nb < 2; nb++) {
                uint32_t r[4];
                ldsm4(r, b_lm + aoffb + (uint32_t)nb * 16 * (SROW * 2) + ks * 32);
                b[nb * 2][0] = r[0]; b[nb * 2][1] = r[1];
                b[nb * 2 + 1][0] = r[2]; b[nb * 2 + 1][1] = r[3];
            }
            #pragma unroll
            for (int mi = 0; mi < 4; mi++)
                #pragma unroll
                for (int ni = 0; ni < 4; ni++)
                    mma16816(acc[mi][ni], a[mi], b[ni]);
        }
    };

    gload(0);
    sstore(0);
    __syncthreads();
    int buf = 0;
    for (int s = 1; s < 48; ++s) {
        gload(s);
        compute(buf);
        buf ^= 1;
        sstore(buf);
        __syncthreads();
    }
    compute(buf);

    // epilogue: C fragment rows grp,+8; cols (lane&3)*2
    #pragma unroll
    for (int mi = 0; mi < 4; mi++) {
        int row0 = bm + warp_m + mi * 16 + (lane >> 2);
        #pragma unroll
        for (int ni = 0; ni < 4; ni++) {
            int col = bn + warp_n + ni * 8 + ((lane & 3) << 1);
            if (row0 < M)
                *(float2*)&C[(size_t)row0 * N + col] = make_float2(acc[mi][ni][0], acc[mi][ni][1]);
            if (row0 + 8 < M)
                *(float2*)&C[(size_t)(row0 + 8) * N + col] = make_float2(acc[mi][ni][2], acc[mi][ni][3]);
        }
    }
}

// ---------------- aggregation ----------------
// out[i] = bias + dis^2*Y[i] + sum val*Y[col]; optionally fused bf16 split into g_A2
template <int D, int RELU, int WB16, int WF32>
__global__ __launch_bounds__(128) void aggregate_kernel(
    const float* __restrict__ Y, float* __restrict__ out, const float* __restrict__ bias) {
    constexpr int TPN = D / 4;
    int gt = blockIdx.x * 128 + threadIdx.x;
    int node = gt / TPN;
    int lane = gt % TPN;
    if (node >= NN) return;
    int c = lane << 2;

    float dv = g_dis[node];
    float w = dv * dv;
    float4 acc = *(const float4*)(bias + c);
    float4 y = *(const float4*)(Y + (size_t)node * D + c);
    acc.x = fmaf(w, y.x, acc.x); acc.y = fmaf(w, y.y, acc.y);
    acc.z = fmaf(w, y.z, acc.z); acc.w = fmaf(w, y.w, acc.w);

    int e0 = g_rowptr[node], e1 = g_rowptr[node + 1];
    for (int p = e0; p < e1; ++p) {
        int j = __ldg(&g_col[p]);
        float v = __ldg(&g_val[p]);
        float4 yj = *(const float4*)(Y + (size_t)j * D + c);
        acc.x = fmaf(v, yj.x, acc.x); acc.y = fmaf(v, yj.y, acc.y);
        acc.z = fmaf(v, yj.z, acc.z); acc.w = fmaf(v, yj.w, acc.w);
    }
    if (RELU) {
        acc.x = fmaxf(acc.x, 0.f); acc.y = fmaxf(acc.y, 0.f);
        acc.z = fmaxf(acc.z, 0.f); acc.w = fmaxf(acc.w, 0.f);
    }
    if (WF32) *(float4*)(out + (size_t)node * D + c) = acc;
    if (WB16) {
        uint2 hi, lo;
        split4(acc, hi, lo);
        *(uint2*)(g_A2 + (size_t)node * 1024 + c) = hi;
        *(uint2*)(g_A2 + (size_t)node * 1024 + 512 + c) = lo;
    }
}

// ---------------- SIMT GEMM for heads (f32x2) ----------------
__device__ __forceinline__ unsigned long long pack2f(float x) {
    unsigned long long r;
    asm("mov.b64 %0, {%1, %1};" : "=l"(r) : "f"(x));
    return r;
}
__device__ __forceinline__ void fma2(unsigned long long& acc, unsigned long long a, unsigned long long b) {
    asm("fma.rn.f32x2 %0, %1, %2, %0;" : "+l"(acc) : "l"(a), "l"(b));
}
__device__ __forceinline__ float2 unpack2(unsigned long long v) {
    float2 r;
    r.x = __uint_as_float((unsigned int)(v & 0xffffffffull));
    r.y = __uint_as_float((unsigned int)(v >> 32));
    return r;
}

__global__ __launch_bounds__(256) void gemm_kernel(
    const float* __restrict__ A, const float* __restrict__ B,
    float* __restrict__ C, const float* __restrict__ bias,
    int M, int N, int K) {
    __shared__ __align__(16) float As[2][16][132];
    __shared__ __align__(16) float Bs[2][16][128];

    const int tid = threadIdx.x;
    const int tx = tid & 15;
    const int ty = tid >> 4;
    const int bm = blockIdx.y * 128;
    const int bn = blockIdx.x * 128;

    const int arow = tid >> 2;
    const int ak = (tid & 3) << 2;
    const int brow = tid >> 5;
    const int bcol = (tid & 31) << 2;
    const bool fullN = (bn + 128 <= N);

    float4 a0, a1, b0, b1;
    auto gload = [&](int kt) {
        int r0 = bm + arow, r1 = r0 + 64;
        a0 = (r0 < M) ? *(const float4*)(A + (size_t)r0 * K + kt + ak) : make_float4(0.f, 0.f, 0.f, 0.f);
        a1 = (r1 < M) ? *(const float4*)(A + (size_t)r1 * K + kt + ak) : make_float4(0.f, 0.f, 0.f, 0.f);
        int c = bn + bcol;
        const float* Bp0 = B + (size_t)(kt + brow) * N;
        const float* Bp1 = B + (size_t)(kt + brow + 8) * N;
        if (fullN) { b0 = *(const float4*)(Bp0 + c); b1 = *(const float4*)(Bp1 + c); }
        else {
            b0.x = (c + 0 < N) ? Bp0[c + 0] : 0.f; b0.y = (c + 1 < N) ? Bp0[c + 1] : 0.f;
            b0.z = (c + 2 < N) ? Bp0[c + 2] : 0.f; b0.w = (c + 3 < N) ? Bp0[c + 3] : 0.f;
            b1.x = (c + 0 < N) ? Bp1[c + 0] : 0.f; b1.y = (c + 1 < N) ? Bp1[c + 1] : 0.f;
            b1.z = (c + 2 < N) ? Bp1[c + 2] : 0.f; b1.w = (c + 3 < N) ? Bp1[c + 3] : 0.f;
        }
    };
    auto sstore = [&](int bi) {
        As[bi][ak + 0][arow] = a0.x; As[bi][ak + 1][arow] = a0.y;
        As[bi][ak + 2][arow] = a0.z; As[bi][ak + 3][arow] = a0.w;
        As[bi][ak + 0][arow + 64] = a1.x; As[bi][ak + 1][arow + 64] = a1.y;
        As[bi][ak + 2][arow + 64] = a1.z; As[bi][ak + 3][arow + 64] = a1.w;
        *(float4*)&Bs[bi][brow][bcol] = b0;
        *(float4*)&Bs[bi][brow + 8][bcol] = b1;
    };

    unsigned long long acc[8][4];
    #pragma unroll
    for (int i = 0; i < 8; i++)
        #pragma unroll
        for (int j = 0; j < 4; j++) acc[i][j] = 0ull;

    auto compute = [&](int bi) {
        #pragma unroll
        for (int k = 0; k < 16; k++) {
            float4 av0 = *(const float4*)&As[bi][k][ty << 2];
            float4 av1 = *(const float4*)&As[bi][k][(ty << 2) + 64];
            ulonglong2 bv0 = *(const ulonglong2*)&Bs[bi][k][tx << 2];
            ulonglong2 bv1 = *(const ulonglong2*)&Bs[bi][k][(tx << 2) + 64];
            unsigned long long ap[8];
            ap[0] = pack2f(av0.x); ap[1] = pack2f(av0.y);
            ap[2] = pack2f(av0.z); ap[3] = pack2f(av0.w);
            ap[4] = pack2f(av1.x); ap[5] = pack2f(av1.y);
            ap[6] = pack2f(av1.z); ap[7] = pack2f(av1.w);
            #pragma unroll
            for (int m = 0; m < 8; m++) {
                fma2(acc[m][0], ap[m], bv0.x);
                fma2(acc[m][1], ap[m], bv0.y);
                fma2(acc[m][2], ap[m], bv1.x);
                fma2(acc[m][3], ap[m], bv1.y);
            }
        }
    };

    gload(0); sstore(0); __syncthreads();
    const int nT = K >> 4;
    int buf = 0;
    for (int t = 1; t < nT; ++t) {
        gload(t << 4);
        compute(buf);
        buf ^= 1;
        sstore(buf);
        __syncthreads();
    }
    compute(buf);

    #pragma unroll
    for (int mi = 0; mi < 8; mi++) {
        int r = bm + (ty << 2) + ((mi < 4) ? mi : (mi - 4 + 64));
        if (r >= M) continue;
        float* Crow = C + (size_t)r * N;
        #pragma unroll
        for (int p = 0; p < 4; p++) {
            int c = bn + (tx << 2) + ((p & 1) << 1) + ((p >> 1) << 6);
            float2 v = unpack2(acc[mi][p]);
            if (c < N) Crow[c] = v.x + (bias ? bias[c] : 0.f);
            if (c + 1 < N) Crow[c + 1] = v.y + (bias ? bias[c + 1] : 0.f);
        }
    }
}

// ---------------- head pack / split ----------------
__global__ void pack_heads_kernel(
    const float* __restrict__ We, const float* __restrict__ be,
    const float* __restrict__ Wh, const float* __restrict__ bh,
    const float* __restrict__ Wg, const float* __restrict__ bg) {
    int idx = blockIdx.x * blockDim.x + threadIdx.x;
    if (idx < 256 * 72) {
        int k = idx / 72, j = idx % 72;
        float v;
        if (j < 7) v = We[k * 7 + j];
        else if (j < 15) v = Wh[k * 8 + (j - 7)];
        else v = Wg[k * 57 + (j - 15)];
        g_Wall[idx] = v;
    }
    if (idx < 72) {
        float v;
        if (idx < 7) v = be[idx];
        else if (idx < 15) v = bh[idx - 7];
        else v = bg[idx - 15];
        g_ball[idx] = v;
    }
}

__global__ void split_heads_kernel(const float* __restrict__ T,
                                   float* __restrict__ outE,
                                   float* __restrict__ outH,
                                   float* __restrict__ outG) {
    int idx = blockIdx.x * blockDim.x + threadIdx.x;
    if (idx >= NN * 72) return;
    int i = idx / 72, j = idx % 72;
    float v = T[idx];
    if (j < 7) outE[i * 7 + j] = v;
    else if (j < 15) outH[i * 8 + (j - 7)] = v;
    else outG[i * 57 + (j - 15)] = v;
}

// ---------------- launch ----------------
extern "C" void kernel_launch(void* const* d_in, const int* in_sizes, int n_in,
                              void* d_out, int out_size) {
    const float* x  = (const float*)d_in[0];
    const int*   ei = (const int*)d_in[1];
    const float* W1 = (const float*)d_in[2];
    const float* b1 = (const float*)d_in[3];
    const float* W2 = (const float*)d_in[4];
    const float* b2 = (const float*)d_in[5];
    const float* W3 = (const float*)d_in[6];
    const float* b3 = (const float*)d_in[7];
    const float* We = (const float*)d_in[8];
    const float* be = (const float*)d_in[9];
    const float* Wh = (const float*)d_in[10];
    const float* bh = (const float*)d_in[11];
    const float* Wg = (const float*)d_in[12];
    const float* bg = (const float*)d_in[13];

    const int* srcArr = ei;
    const int* dstArr = ei + NE;

    float* out  = (float*)d_out;
    float* emb  = out;
    float* outE = out + (size_t)NN * 256;
    float* outH = outE + (size_t)NN * 7;
    float* outG = outH + (size_t)NN * 8;

    float *buf1, *buf2, *Wall, *ball;
    __nv_bfloat16 *A2, *Bt1, *Bt2, *Bt3;
    cudaGetSymbolAddress((void**)&buf1, g_buf1);
    cudaGetSymbolAddress((void**)&buf2, g_buf2);
    cudaGetSymbolAddress((void**)&Wall, g_Wall);
    cudaGetSymbolAddress((void**)&ball, g_ball);
    cudaGetSymbolAddress((void**)&A2,  g_A2);
    cudaGetSymbolAddress((void**)&Bt1, g_Bt1);
    cudaGetSymbolAddress((void**)&Bt2, g_Bt2);
    cudaGetSymbolAddress((void**)&Bt3, g_Bt3);

    // weight conversions (independent of CSR)
    convert_B_kernel<<<(512 * 512 + 255) / 256, 256>>>(W1, Bt1, 512);
    convert_B_kernel<<<(512 * 512 + 255) / 256, 256>>>(W2, Bt2, 512);
    convert_B_kernel<<<(512 * 256 + 255) / 256, 256>>>(W3, Bt3, 256);

    // CSR build
    zero_indeg_kernel<<<(NN + 255) / 256, 256>>>();
    count_kernel<<<(NE + 255) / 256, 256>>>(dstArr);
    dis_kernel<<<(NN + 255) / 256, 256>>>();
    scan_part1<<<49, 1024>>>();
    scan_part2<<<1, 1>>>();
    scan_part3<<<49, 1024>>>();
    scatter_kernel<<<(NE + 255) / 256, 256>>>(srcArr, dstArr);

    const int gm = MPAD / 128;  // 391

    // layer 1
    convert_x_kernel<<<(MPAD * 128 + 255) / 256, 256>>>(x);
    gemm_mma_kernel<<<dim3(4, gm), 256>>>(A2, Bt1, buf1, NN, 512);
    aggregate_kernel<512, 1, 1, 0><<<NN, 128>>>(buf1, nullptr, b1);  // -> g_A2 (bf16 split)
    // layer 2
    gemm_mma_kernel<<<dim3(4, gm), 256>>>(A2, Bt2, buf1, NN, 512);
    aggregate_kernel<512, 1, 1, 0><<<NN, 128>>>(buf1, nullptr, b2);  // -> g_A2 (bf16 split)
    // layer 3 (emb f32, no relu)
    gemm_mma_kernel<<<dim3(2, gm), 256>>>(A2, Bt3, buf1, NN, 256);
    aggregate_kernel<256, 0, 0, 1><<<NN / 2, 128>>>(buf1, emb, b3);
    // heads
    pack_heads_kernel<<<(256 * 72 + 255) / 256, 256>>>(We, be, Wh, bh, Wg, bg);
    gemm_kernel<<<dim3(1, (NN + 127) / 128), 256>>>(emb, Wall, buf2, ball, NN, 72, 256);
    split_heads_kernel<<<(NN * 72 + 255) / 256, 256>>>(buf2, outE, outH, outG);
}